// round 8
// baseline (speedup 1.0000x reference)
#include <cuda_runtime.h>
#include <cuda_bf16.h>
#include <mma.h>

using namespace nvcuda;

#define T_TOK 4096
#define D_DIM 768
#define H_DIM 2688
#define E_NUM 8
#define BK 16

// ---------------- scratch (static device globals; no allocations) ----------------
__device__ float g_z_acc;
__device__ int   g_cnt[E_NUM];
__device__ int   g_tok[E_NUM * T_TOK];
__device__ int   g_slot[2 * T_TOK];   // per token: two (expert*T_TOK + pos) slots
__device__ float g_wt [2 * T_TOK];    // per token: two softmax weights
// act scratch: [E*T, H] fp32 (tf32-rounded)
__device__ float g_act[(size_t)E_NUM * T_TOK * H_DIM];
// per-slot down-proj result: [E*T, D] fp32
__device__ float g_y[(size_t)E_NUM * T_TOK * D_DIM];

__device__ __forceinline__ void cvt_sts4(float* d, float4 v) {
    d[0] = wmma::__float_to_tf32(v.x);
    d[1] = wmma::__float_to_tf32(v.y);
    d[2] = wmma::__float_to_tf32(v.z);
    d[3] = wmma::__float_to_tf32(v.w);
}

// ---------------- kernel 0: init counters ----------------
__global__ void k_init() {
    if (threadIdx.x < E_NUM) g_cnt[threadIdx.x] = 0;
    if (threadIdx.x == 31)   g_z_acc = 0.0f;
}

// ---------------- kernel 1: router ----------------
__global__ void k_router(const float* __restrict__ x,
                         const float* __restrict__ gw,
                         const float* __restrict__ bias) {
    int gwarp = (blockIdx.x * blockDim.x + threadIdx.x) >> 5;
    int lane  = threadIdx.x & 31;
    if (gwarp >= T_TOK) return;
    const float* xr = x + (size_t)gwarp * D_DIM;

    float xv[24];
#pragma unroll
    for (int i = 0; i < 24; i++) xv[i] = xr[i * 32 + lane];

    float lg[8];
#pragma unroll
    for (int e = 0; e < 8; e++) {
        const float* w = gw + e * D_DIM;
        float s = 0.0f;
#pragma unroll
        for (int i = 0; i < 24; i++) s += xv[i] * w[i * 32 + lane];
#pragma unroll
        for (int o = 16; o > 0; o >>= 1) s += __shfl_xor_sync(0xffffffffu, s, o);
        lg[e] = s;
    }

    if (lane == 0) {
        float b1 = -1e30f, b2 = -1e30f; int i1 = 0, i2 = 0;
#pragma unroll
        for (int e = 0; e < 8; e++) {
            float b = lg[e] + bias[e];
            if (b > b1)      { b2 = b1; i2 = i1; b1 = b; i1 = e; }
            else if (b > b2) { b2 = b;  i2 = e; }
        }
        float l1 = lg[i1], l2 = lg[i2];
        float m = fmaxf(l1, l2);
        float e1 = expf(l1 - m), e2 = expf(l2 - m);
        float inv = 1.0f / (e1 + e2);
        float w1 = e1 * inv, w2 = e2 * inv;

        float mm = lg[0];
#pragma unroll
        for (int e = 1; e < 8; e++) mm = fmaxf(mm, lg[e]);
        float s = 0.0f;
#pragma unroll
        for (int e = 0; e < 8; e++) s += expf(lg[e] - mm);
        float lse = mm + logf(s);
        atomicAdd(&g_z_acc, lse * lse);

        int p1 = atomicAdd(&g_cnt[i1], 1);
        g_tok[i1 * T_TOK + p1] = gwarp;
        g_slot[2 * gwarp + 0] = i1 * T_TOK + p1;
        g_wt  [2 * gwarp + 0] = w1;
        int p2 = atomicAdd(&g_cnt[i2], 1);
        g_tok[i2 * T_TOK + p2] = gwarp;
        g_slot[2 * gwarp + 1] = i2 * T_TOK + p2;
        g_wt  [2 * gwarp + 1] = w2;
    }
}

// ---------------- kernel 2: grouped GEMM1, 128x64 tiles, double-buffered ----------------
// block: expert e, 128 gathered tokens, 64 hidden dims. g = X*Wg, u = X*Wu,
// act = silu(g)*u -> g_act (tf32-rounded, stored direct from fragments).
__global__ void __launch_bounds__(256) k_gemm1(const float* __restrict__ x,
                                               const float* __restrict__ wgate,
                                               const float* __restrict__ wup) {
    const int e   = blockIdx.z;
    const int cnt = g_cnt[e];
    const int m0  = blockIdx.x * 128;
    if (m0 >= cnt) return;
    const int n0  = blockIdx.y * 64;

    __shared__ float sA [2][128][20];
    __shared__ float sBg[2][BK][68];
    __shared__ float sBu[2][BK][68];

    const int tid  = threadIdx.x;
    const int warp = tid >> 5;
    const int wm   = warp >> 1;   // 0..3 -> 32-row slab
    const int wn   = warp & 1;    // 0..1 -> 32-col slab

    // A staging: 2 float4/thread. lin = q*256+tid; row = lin>>2; c4 = lin&3
    const float* a_ptr[2];
#pragma unroll
    for (int q = 0; q < 2; q++) {
        int lin = q * 256 + tid;
        int r = lin >> 2, c4 = lin & 3;
        int row = m0 + r;
        int tok = g_tok[e * T_TOK + (row < cnt ? row : 0)];
        a_ptr[q] = x + (size_t)tok * D_DIM + c4 * 4;
    }
    // B staging: 1 float4/thread/matrix. row = tid>>4; c4 = tid&15
    const int b_r = tid >> 4, b_c4 = tid & 15;
    const size_t wb = (size_t)e * D_DIM * H_DIM;
    const float* bg_ptr = wgate + wb + (size_t)b_r * H_DIM + n0 + b_c4 * 4;
    const float* bu_ptr = wup   + wb + (size_t)b_r * H_DIM + n0 + b_c4 * 4;

    wmma::fragment<wmma::accumulator, 16, 16, 8, float> accg[2][2], accu[2][2];
#pragma unroll
    for (int i = 0; i < 2; i++)
#pragma unroll
        for (int j = 0; j < 2; j++) {
            wmma::fill_fragment(accg[i][j], 0.0f);
            wmma::fill_fragment(accu[i][j], 0.0f);
        }

    float4 ra[2], rg, ru;
    // prologue: load kt=0, fill stage 0
    ra[0] = *(const float4*)a_ptr[0];
    ra[1] = *(const float4*)a_ptr[1];
    rg = *(const float4*)bg_ptr;
    ru = *(const float4*)bu_ptr;
    a_ptr[0] += BK; a_ptr[1] += BK;
    bg_ptr += (size_t)BK * H_DIM; bu_ptr += (size_t)BK * H_DIM;
#pragma unroll
    for (int q = 0; q < 2; q++) {
        int lin = q * 256 + tid;
        cvt_sts4(&sA[0][lin >> 2][(lin & 3) * 4], ra[q]);
    }
    cvt_sts4(&sBg[0][b_r][b_c4 * 4], rg);
    cvt_sts4(&sBu[0][b_r][b_c4 * 4], ru);
    __syncthreads();

    const int NK = D_DIM / BK;   // 48
    for (int kt = 0; kt < NK; kt++) {
        const int cur = kt & 1;
        if (kt + 1 < NK) {
            ra[0] = *(const float4*)a_ptr[0];
            ra[1] = *(const float4*)a_ptr[1];
            rg = *(const float4*)bg_ptr;
            ru = *(const float4*)bu_ptr;
            a_ptr[0] += BK; a_ptr[1] += BK;
            bg_ptr += (size_t)BK * H_DIM; bu_ptr += (size_t)BK * H_DIM;
        }
#pragma unroll
        for (int kk = 0; kk < 2; kk++) {
            wmma::fragment<wmma::matrix_a, 16, 16, 8, wmma::precision::tf32, wmma::row_major> af[2];
            wmma::fragment<wmma::matrix_b, 16, 16, 8, wmma::precision::tf32, wmma::row_major> bgf[2], buf2[2];
#pragma unroll
            for (int i = 0; i < 2; i++)
                wmma::load_matrix_sync(af[i], &sA[cur][wm * 32 + i * 16][kk * 8], 20);
#pragma unroll
            for (int j = 0; j < 2; j++) {
                wmma::load_matrix_sync(bgf[j],  &sBg[cur][kk * 8][wn * 32 + j * 16], 68);
                wmma::load_matrix_sync(buf2[j], &sBu[cur][kk * 8][wn * 32 + j * 16], 68);
            }
#pragma unroll
            for (int i = 0; i < 2; i++)
#pragma unroll
                for (int j = 0; j < 2; j++) {
                    wmma::mma_sync(accg[i][j], af[i], bgf[j],  accg[i][j]);
                    wmma::mma_sync(accu[i][j], af[i], buf2[j], accu[i][j]);
                }
        }
        if (kt + 1 < NK) {
            const int nxt = (kt + 1) & 1;
#pragma unroll
            for (int q = 0; q < 2; q++) {
                int lin = q * 256 + tid;
                cvt_sts4(&sA[nxt][lin >> 2][(lin & 3) * 4], ra[q]);
            }
            cvt_sts4(&sBg[nxt][b_r][b_c4 * 4], rg);
            cvt_sts4(&sBu[nxt][b_r][b_c4 * 4], ru);
        }
        __syncthreads();
    }

    // epilogue: act = round_tf32(silu(g) * u), store fragments direct to global.
    // rows beyond cnt write in-bounds junk (never read by gemm2's valid rows).
    float* cbase = g_act + (size_t)(e * T_TOK + m0) * H_DIM + n0;
#pragma unroll
    for (int i = 0; i < 2; i++)
#pragma unroll
        for (int j = 0; j < 2; j++) {
#pragma unroll
            for (int t = 0; t < accg[i][j].num_elements; t++) {
                float g = accg[i][j].x[t];
                float u = accu[i][j].x[t];
                float sg = 1.0f / (1.0f + expf(-g));
                accg[i][j].x[t] = wmma::__float_to_tf32(g * sg * u);
            }
            wmma::store_matrix_sync(cbase + (size_t)(wm * 32 + i * 16) * H_DIM + wn * 32 + j * 16,
                                    accg[i][j], H_DIM, wmma::mem_row_major);
        }
}

// ---------------- kernel 3: grouped GEMM2, 128x128 tiles, double-buffered ----------------
// grid.x = N-tiles (6) so per-expert A slab + wdown slab stay hot in L2.
__global__ void __launch_bounds__(256) k_gemm2(const float* __restrict__ wdown) {
    const int e   = blockIdx.z;
    const int cnt = g_cnt[e];
    const int m0  = blockIdx.y * 128;
    if (m0 >= cnt) return;
    const int n0  = blockIdx.x * 128;

    __shared__ float sA[2][128][20];
    __shared__ float sB[2][BK][136];

    const int tid  = threadIdx.x;
    const int warp = tid >> 5;
    const int wm   = warp >> 2;   // 0..1 -> 64-row slab
    const int wn   = warp & 3;    // 0..3 -> 32-col slab

    // A staging: 2 float4/thread, dense rows of g_act (already tf32-rounded)
    const float* a_ptr[2];
#pragma unroll
    for (int q = 0; q < 2; q++) {
        int lin = q * 256 + tid;
        int r = lin >> 2, c4 = lin & 3;
        a_ptr[q] = g_act + (size_t)(e * T_TOK + m0 + r) * H_DIM + c4 * 4;
    }
    // B staging: 2 float4/thread. lin = q*256+tid; row = lin>>5; c4 = lin&31
    const float* b_ptr[2];
#pragma unroll
    for (int q = 0; q < 2; q++) {
        int lin = q * 256 + tid;
        int r = lin >> 5, c4 = lin & 31;
        b_ptr[q] = wdown + (size_t)e * H_DIM * D_DIM + (size_t)r * D_DIM + n0 + c4 * 4;
    }

    wmma::fragment<wmma::accumulator, 16, 16, 8, float> acc[4][2];
#pragma unroll
    for (int i = 0; i < 4; i++)
#pragma unroll
        for (int j = 0; j < 2; j++) wmma::fill_fragment(acc[i][j], 0.0f);

    float4 ra[2], rb[2];
    // prologue
#pragma unroll
    for (int q = 0; q < 2; q++) { ra[q] = *(const float4*)a_ptr[q]; a_ptr[q] += BK; }
#pragma unroll
    for (int q = 0; q < 2; q++) { rb[q] = *(const float4*)b_ptr[q]; b_ptr[q] += (size_t)BK * D_DIM; }
#pragma unroll
    for (int q = 0; q < 2; q++) {
        int lin = q * 256 + tid;
        *(float4*)&sA[0][lin >> 2][(lin & 3) * 4] = ra[q];     // already tf32
        cvt_sts4(&sB[0][lin >> 5][(lin & 31) * 4], rb[q]);
    }
    __syncthreads();

    const int NK = H_DIM / BK;   // 168
    for (int kt = 0; kt < NK; kt++) {
        const int cur = kt & 1;
        if (kt + 1 < NK) {
#pragma unroll
            for (int q = 0; q < 2; q++) { ra[q] = *(const float4*)a_ptr[q]; a_ptr[q] += BK; }
#pragma unroll
            for (int q = 0; q < 2; q++) { rb[q] = *(const float4*)b_ptr[q]; b_ptr[q] += (size_t)BK * D_DIM; }
        }
#pragma unroll
        for (int kk = 0; kk < 2; kk++) {
            wmma::fragment<wmma::matrix_a, 16, 16, 8, wmma::precision::tf32, wmma::row_major> af[4];
            wmma::fragment<wmma::matrix_b, 16, 16, 8, wmma::precision::tf32, wmma::row_major> bf[2];
#pragma unroll
            for (int i = 0; i < 4; i++)
                wmma::load_matrix_sync(af[i], &sA[cur][wm * 64 + i * 16][kk * 8], 20);
#pragma unroll
            for (int j = 0; j < 2; j++)
                wmma::load_matrix_sync(bf[j], &sB[cur][kk * 8][wn * 32 + j * 16], 136);
#pragma unroll
            for (int i = 0; i < 4; i++)
#pragma unroll
                for (int j = 0; j < 2; j++)
                    wmma::mma_sync(acc[i][j], af[i], bf[j], acc[i][j]);
        }
        if (kt + 1 < NK) {
            const int nxt = (kt + 1) & 1;
#pragma unroll
            for (int q = 0; q < 2; q++) {
                int lin = q * 256 + tid;
                *(float4*)&sA[nxt][lin >> 2][(lin & 3) * 4] = ra[q];
                cvt_sts4(&sB[nxt][lin >> 5][(lin & 31) * 4], rb[q]);
            }
        }
        __syncthreads();
    }

    // epilogue: store per-slot result direct to g_y (no atomics, no masking —
    // junk rows land in-bounds and are never read by combine)
    float* ybase = g_y + (size_t)(e * T_TOK + m0) * D_DIM + n0;
#pragma unroll
    for (int i = 0; i < 4; i++)
#pragma unroll
        for (int j = 0; j < 2; j++)
            wmma::store_matrix_sync(ybase + (size_t)(wm * 64 + i * 16) * D_DIM + wn * 32 + j * 16,
                                    acc[i][j], D_DIM, wmma::mem_row_major);
}

// ---------------- kernel 4: combine two expert slots per token ----------------
__global__ void k_combine(float* __restrict__ out) {
    const int t = blockIdx.x;
    const int s0 = g_slot[2 * t], s1 = g_slot[2 * t + 1];
    const float w0 = g_wt[2 * t], w1 = g_wt[2 * t + 1];
    const float4* y0 = (const float4*)(g_y + (size_t)s0 * D_DIM);
    const float4* y1 = (const float4*)(g_y + (size_t)s1 * D_DIM);
    float4 a = y0[threadIdx.x];
    float4 b = y1[threadIdx.x];
    float4 r;
    r.x = w0 * a.x + w1 * b.x;
    r.y = w0 * a.y + w1 * b.y;
    r.z = w0 * a.z + w1 * b.z;
    r.w = w0 * a.w + w1 * b.w;
    ((float4*)(out + (size_t)t * D_DIM))[threadIdx.x] = r;
}

// ---------------- kernel 5: finalize z-loss ----------------
__global__ void k_final(float* __restrict__ out, int out_size) {
    if (out_size > T_TOK * D_DIM)
        out[T_TOK * D_DIM] = 1e-5f * g_z_acc / (float)T_TOK;
}

// ---------------- launcher ----------------
extern "C" void kernel_launch(void* const* d_in, const int* in_sizes, int n_in,
                              void* d_out, int out_size) {
    const float* x     = (const float*)d_in[0];  // [2,2048,768]
    const float* gw    = (const float*)d_in[1];  // [8,768]
    const float* bias  = (const float*)d_in[2];  // [8]
    const float* wgate = (const float*)d_in[3];  // [8,768,2688]
    const float* wup   = (const float*)d_in[4];  // [8,768,2688]
    const float* wdown = (const float*)d_in[5];  // [8,2688,768]
    float* out = (float*)d_out;

    k_init<<<1, 32>>>();
    k_router<<<T_TOK / 8, 256>>>(x, gw, bias);

    dim3 g1(T_TOK / 128, H_DIM / 64, E_NUM);   // 32 x 42 x 8 (M-tiles adjacent -> weight-slab L2 reuse)
    k_gemm1<<<g1, 256>>>(x, wgate, wup);

    dim3 g2(D_DIM / 128, T_TOK / 128, E_NUM);  // 6 x 32 x 8 (N fastest -> A-slab L2 reuse)
    k_gemm2<<<g2, 256>>>(wdown);

    k_combine<<<T_TOK, 192>>>(out);
    k_final<<<1, 1>>>(out, out_size);
}

// round 9
// speedup vs baseline: 1.9533x; 1.9533x over previous
#include <cuda_runtime.h>
#include <cuda_bf16.h>
#include <mma.h>

using namespace nvcuda;

#define T_TOK 4096
#define D_DIM 768
#define H_DIM 2688
#define E_NUM 8
#define BK 16

// ---------------- scratch (static device globals; no allocations) ----------------
__device__ float g_z_acc;
__device__ int   g_cnt[E_NUM];
__device__ int   g_tok[E_NUM * T_TOK];
__device__ int   g_slot[2 * T_TOK];   // per token: two (expert*T_TOK + pos) slots
__device__ float g_wt [2 * T_TOK];    // per token: two softmax weights
// tf32-rounded copies (RN) so GEMM loops can cp.async raw bytes
__device__ float g_x32 [(size_t)T_TOK * D_DIM];
__device__ float g_wg32[(size_t)E_NUM * D_DIM * H_DIM];
__device__ float g_wu32[(size_t)E_NUM * D_DIM * H_DIM];
__device__ float g_wd32[(size_t)E_NUM * H_DIM * D_DIM];
// act scratch: [E*T, H] fp32 (tf32-rounded)
__device__ float g_act[(size_t)E_NUM * T_TOK * H_DIM];
// per-slot down-proj result: [E*T, D] fp32
__device__ float g_y[(size_t)E_NUM * T_TOK * D_DIM];

__device__ __forceinline__ void cpa16(float* s, const float* g) {
    unsigned a = (unsigned)__cvta_generic_to_shared(s);
    asm volatile("cp.async.cg.shared.global [%0], [%1], 16;" :: "r"(a), "l"(g));
}
#define CP_COMMIT() asm volatile("cp.async.commit_group;" ::: "memory")
#define CP_WAIT1()  asm volatile("cp.async.wait_group 1;" ::: "memory")

__device__ __forceinline__ float4 cvt4(float4 v) {
    float4 r;
    r.x = wmma::__float_to_tf32(v.x);
    r.y = wmma::__float_to_tf32(v.y);
    r.z = wmma::__float_to_tf32(v.z);
    r.w = wmma::__float_to_tf32(v.w);
    return r;
}

// ---------------- kernel 0: init counters ----------------
__global__ void k_init() {
    if (threadIdx.x < E_NUM) g_cnt[threadIdx.x] = 0;
    if (threadIdx.x == 31)   g_z_acc = 0.0f;
}

// ---------------- kernel 0b: RN-round inputs/weights to tf32 copies ----------------
__global__ void k_cvt(const float* __restrict__ x,
                      const float* __restrict__ wg,
                      const float* __restrict__ wu,
                      const float* __restrict__ wd) {
    const size_t i0 = (size_t)blockIdx.x * blockDim.x + threadIdx.x;
    const size_t st = (size_t)gridDim.x * blockDim.x;
    const size_t NX = (size_t)T_TOK * D_DIM / 4;
    const size_t NW = (size_t)E_NUM * D_DIM * H_DIM / 4;
    for (size_t i = i0; i < NX; i += st)
        ((float4*)g_x32)[i] = cvt4(((const float4*)x)[i]);
    for (size_t i = i0; i < NW; i += st)
        ((float4*)g_wg32)[i] = cvt4(((const float4*)wg)[i]);
    for (size_t i = i0; i < NW; i += st)
        ((float4*)g_wu32)[i] = cvt4(((const float4*)wu)[i]);
    for (size_t i = i0; i < NW; i += st)
        ((float4*)g_wd32)[i] = cvt4(((const float4*)wd)[i]);
}

// ---------------- kernel 1: router ----------------
__global__ void k_router(const float* __restrict__ x,
                         const float* __restrict__ gw,
                         const float* __restrict__ bias) {
    int gwarp = (blockIdx.x * blockDim.x + threadIdx.x) >> 5;
    int lane  = threadIdx.x & 31;
    if (gwarp >= T_TOK) return;
    const float* xr = x + (size_t)gwarp * D_DIM;

    float xv[24];
#pragma unroll
    for (int i = 0; i < 24; i++) xv[i] = xr[i * 32 + lane];

    float lg[8];
#pragma unroll
    for (int e = 0; e < 8; e++) {
        const float* w = gw + e * D_DIM;
        float s = 0.0f;
#pragma unroll
        for (int i = 0; i < 24; i++) s += xv[i] * w[i * 32 + lane];
#pragma unroll
        for (int o = 16; o > 0; o >>= 1) s += __shfl_xor_sync(0xffffffffu, s, o);
        lg[e] = s;
    }

    if (lane == 0) {
        float b1 = -1e30f, b2 = -1e30f; int i1 = 0, i2 = 0;
#pragma unroll
        for (int e = 0; e < 8; e++) {
            float b = lg[e] + bias[e];
            if (b > b1)      { b2 = b1; i2 = i1; b1 = b; i1 = e; }
            else if (b > b2) { b2 = b;  i2 = e; }
        }
        float l1 = lg[i1], l2 = lg[i2];
        float m = fmaxf(l1, l2);
        float e1 = expf(l1 - m), e2 = expf(l2 - m);
        float inv = 1.0f / (e1 + e2);
        float w1 = e1 * inv, w2 = e2 * inv;

        float mm = lg[0];
#pragma unroll
        for (int e = 1; e < 8; e++) mm = fmaxf(mm, lg[e]);
        float s = 0.0f;
#pragma unroll
        for (int e = 0; e < 8; e++) s += expf(lg[e] - mm);
        float lse = mm + logf(s);
        atomicAdd(&g_z_acc, lse * lse);

        int p1 = atomicAdd(&g_cnt[i1], 1);
        g_tok[i1 * T_TOK + p1] = gwarp;
        g_slot[2 * gwarp + 0] = i1 * T_TOK + p1;
        g_wt  [2 * gwarp + 0] = w1;
        int p2 = atomicAdd(&g_cnt[i2], 1);
        g_tok[i2 * T_TOK + p2] = gwarp;
        g_slot[2 * gwarp + 1] = i2 * T_TOK + p2;
        g_wt  [2 * gwarp + 1] = w2;
    }
}

// ---------------- kernel 2: grouped GEMM1, 64x64 tile, cp.async 3-stage ----------------
// g = X*Wg, u = X*Wu (shared A), act = silu(g)*u -> g_act, one barrier per K-step.
__global__ void __launch_bounds__(128) k_gemm1() {
    const int e   = blockIdx.z;
    const int cnt = g_cnt[e];
    const int m0  = blockIdx.x * 64;
    if (m0 >= cnt) return;
    const int n0  = blockIdx.y * 64;

    __shared__ float sA [3][64][20];
    __shared__ float sBg[3][16][68];
    __shared__ float sBu[3][16][68];

    const int tid  = threadIdx.x;
    const int warp = tid >> 5;
    const int wm   = warp >> 1;   // 0..1 -> 32-row slab
    const int wn   = warp & 1;    // 0..1 -> 32-col slab

    // A staging: 2 16B-chunks/thread. chunk = q*128+tid -> row = chunk>>2, c = (chunk&3)*4
    int    a_r[2], a_c[2];
    size_t a_off[2];
#pragma unroll
    for (int q = 0; q < 2; q++) {
        int chunk = q * 128 + tid;
        a_r[q] = chunk >> 2; a_c[q] = (chunk & 3) * 4;
        int row = m0 + a_r[q];
        int tok = g_tok[e * T_TOK + (row < cnt ? row : cnt - 1)];
        a_off[q] = (size_t)tok * D_DIM + a_c[q];
    }
    // B staging: 2 chunks/thread/matrix. chunk -> row = chunk>>4, c = (chunk&15)*4
    int    b_r[2], b_c[2];
    size_t b_off[2];
    const size_t wb = (size_t)e * D_DIM * H_DIM;
#pragma unroll
    for (int q = 0; q < 2; q++) {
        int chunk = q * 128 + tid;
        b_r[q] = chunk >> 4; b_c[q] = (chunk & 15) * 4;
        b_off[q] = wb + (size_t)b_r[q] * H_DIM + n0 + b_c[q];
    }

    wmma::fragment<wmma::accumulator, 16, 16, 8, float> accg[2][2], accu[2][2];
#pragma unroll
    for (int i = 0; i < 2; i++)
#pragma unroll
        for (int j = 0; j < 2; j++) {
            wmma::fill_fragment(accg[i][j], 0.0f);
            wmma::fill_fragment(accu[i][j], 0.0f);
        }

    auto issue = [&](int s, int kt) {
        const int k0 = kt * BK;
#pragma unroll
        for (int q = 0; q < 2; q++)
            cpa16(&sA[s][a_r[q]][a_c[q]], g_x32 + a_off[q] + k0);
#pragma unroll
        for (int q = 0; q < 2; q++) {
            const size_t o = b_off[q] + (size_t)k0 * H_DIM;
            cpa16(&sBg[s][b_r[q]][b_c[q]], g_wg32 + o);
            cpa16(&sBu[s][b_r[q]][b_c[q]], g_wu32 + o);
        }
    };

    const int NK = D_DIM / BK;   // 48
    issue(0, 0); CP_COMMIT();
    issue(1, 1); CP_COMMIT();

    for (int kt = 0; kt < NK; kt++) {
        const int cur = kt % 3;
        CP_WAIT1();
        __syncthreads();
        if (kt + 2 < NK) issue((kt + 2) % 3, kt + 2);
        CP_COMMIT();
#pragma unroll
        for (int kk = 0; kk < 2; kk++) {
            wmma::fragment<wmma::matrix_a, 16, 16, 8, wmma::precision::tf32, wmma::row_major> af[2];
            wmma::fragment<wmma::matrix_b, 16, 16, 8, wmma::precision::tf32, wmma::row_major> bgf[2], buf2[2];
#pragma unroll
            for (int i = 0; i < 2; i++)
                wmma::load_matrix_sync(af[i], &sA[cur][wm * 32 + i * 16][kk * 8], 20);
#pragma unroll
            for (int j = 0; j < 2; j++) {
                wmma::load_matrix_sync(bgf[j],  &sBg[cur][kk * 8][wn * 32 + j * 16], 68);
                wmma::load_matrix_sync(buf2[j], &sBu[cur][kk * 8][wn * 32 + j * 16], 68);
            }
#pragma unroll
            for (int i = 0; i < 2; i++)
#pragma unroll
                for (int j = 0; j < 2; j++) {
                    wmma::mma_sync(accg[i][j], af[i], bgf[j],  accg[i][j]);
                    wmma::mma_sync(accu[i][j], af[i], buf2[j], accu[i][j]);
                }
        }
    }

    // epilogue: act = round_tf32(silu(g)*u) direct to g_act (junk rows in-bounds, never read)
    float* cbase = g_act + (size_t)(e * T_TOK + m0) * H_DIM + n0;
#pragma unroll
    for (int i = 0; i < 2; i++)
#pragma unroll
        for (int j = 0; j < 2; j++) {
#pragma unroll
            for (int t = 0; t < accg[i][j].num_elements; t++) {
                float g = accg[i][j].x[t];
                float u = accu[i][j].x[t];
                float sg = 1.0f / (1.0f + expf(-g));
                accg[i][j].x[t] = wmma::__float_to_tf32(g * sg * u);
            }
            wmma::store_matrix_sync(cbase + (size_t)(wm * 32 + i * 16) * H_DIM + wn * 32 + j * 16,
                                    accg[i][j], H_DIM, wmma::mem_row_major);
        }
}

// ---------------- kernel 3: grouped GEMM2, 64x128 tile, cp.async 3-stage ----------------
__global__ void __launch_bounds__(128) k_gemm2() {
    const int e   = blockIdx.z;
    const int cnt = g_cnt[e];
    const int m0  = blockIdx.y * 64;
    if (m0 >= cnt) return;
    const int n0  = blockIdx.x * 128;

    __shared__ float sA[3][64][20];
    __shared__ float sB[3][16][136];

    const int tid  = threadIdx.x;
    const int warp = tid >> 5;
    const int wm   = warp >> 1;   // 0..1 -> 32-row slab
    const int wn   = warp & 1;    // 0..1 -> 64-col slab

    // A staging: 2 chunks/thread from g_act (dense rows, already tf32)
    int    a_r[2], a_c[2];
    size_t a_off[2];
#pragma unroll
    for (int q = 0; q < 2; q++) {
        int chunk = q * 128 + tid;
        a_r[q] = chunk >> 2; a_c[q] = (chunk & 3) * 4;
        a_off[q] = (size_t)(e * T_TOK + m0 + a_r[q]) * H_DIM + a_c[q];
    }
    // B staging: 4 chunks/thread. chunk -> row = chunk>>5, c = (chunk&31)*4
    int    b_r[4], b_c[4];
    size_t b_off[4];
    const size_t wb = (size_t)e * H_DIM * D_DIM;
#pragma unroll
    for (int q = 0; q < 4; q++) {
        int chunk = q * 128 + tid;
        b_r[q] = chunk >> 5; b_c[q] = (chunk & 31) * 4;
        b_off[q] = wb + (size_t)b_r[q] * D_DIM + n0 + b_c[q];
    }

    wmma::fragment<wmma::accumulator, 16, 16, 8, float> acc[2][4];
#pragma unroll
    for (int i = 0; i < 2; i++)
#pragma unroll
        for (int j = 0; j < 4; j++) wmma::fill_fragment(acc[i][j], 0.0f);

    auto issue = [&](int s, int kt) {
        const int k0 = kt * BK;
#pragma unroll
        for (int q = 0; q < 2; q++)
            cpa16(&sA[s][a_r[q]][a_c[q]], g_act + a_off[q] + k0);
#pragma unroll
        for (int q = 0; q < 4; q++)
            cpa16(&sB[s][b_r[q]][b_c[q]], g_wd32 + b_off[q] + (size_t)k0 * D_DIM);
    };

    const int NK = H_DIM / BK;   // 168
    issue(0, 0); CP_COMMIT();
    issue(1, 1); CP_COMMIT();

    for (int kt = 0; kt < NK; kt++) {
        const int cur = kt % 3;
        CP_WAIT1();
        __syncthreads();
        if (kt + 2 < NK) issue((kt + 2) % 3, kt + 2);
        CP_COMMIT();
#pragma unroll
        for (int kk = 0; kk < 2; kk++) {
            wmma::fragment<wmma::matrix_a, 16, 16, 8, wmma::precision::tf32, wmma::row_major> af[2];
            wmma::fragment<wmma::matrix_b, 16, 16, 8, wmma::precision::tf32, wmma::row_major> bf[4];
#pragma unroll
            for (int i = 0; i < 2; i++)
                wmma::load_matrix_sync(af[i], &sA[cur][wm * 32 + i * 16][kk * 8], 20);
#pragma unroll
            for (int j = 0; j < 4; j++)
                wmma::load_matrix_sync(bf[j], &sB[cur][kk * 8][wn * 64 + j * 16], 136);
#pragma unroll
            for (int i = 0; i < 2; i++)
#pragma unroll
                for (int j = 0; j < 4; j++)
                    wmma::mma_sync(acc[i][j], af[i], bf[j], acc[i][j]);
        }
    }

    // epilogue: per-slot result direct to g_y (no atomics; junk rows never combined)
    float* ybase = g_y + (size_t)(e * T_TOK + m0) * D_DIM + n0;
#pragma unroll
    for (int i = 0; i < 2; i++)
#pragma unroll
        for (int j = 0; j < 4; j++)
            wmma::store_matrix_sync(ybase + (size_t)(wm * 32 + i * 16) * D_DIM + wn * 64 + j * 16,
                                    acc[i][j], D_DIM, wmma::mem_row_major);
}

// ---------------- kernel 4: combine two expert slots per token ----------------
__global__ void k_combine(float* __restrict__ out) {
    const int t = blockIdx.x;
    const int s0 = g_slot[2 * t], s1 = g_slot[2 * t + 1];
    const float w0 = g_wt[2 * t], w1 = g_wt[2 * t + 1];
    const float4* y0 = (const float4*)(g_y + (size_t)s0 * D_DIM);
    const float4* y1 = (const float4*)(g_y + (size_t)s1 * D_DIM);
    float4 a = y0[threadIdx.x];
    float4 b = y1[threadIdx.x];
    float4 r;
    r.x = w0 * a.x + w1 * b.x;
    r.y = w0 * a.y + w1 * b.y;
    r.z = w0 * a.z + w1 * b.z;
    r.w = w0 * a.w + w1 * b.w;
    ((float4*)(out + (size_t)t * D_DIM))[threadIdx.x] = r;
}

// ---------------- kernel 5: finalize z-loss ----------------
__global__ void k_final(float* __restrict__ out, int out_size) {
    if (out_size > T_TOK * D_DIM)
        out[T_TOK * D_DIM] = 1e-5f * g_z_acc / (float)T_TOK;
}

// ---------------- launcher ----------------
extern "C" void kernel_launch(void* const* d_in, const int* in_sizes, int n_in,
                              void* d_out, int out_size) {
    const float* x     = (const float*)d_in[0];  // [2,2048,768]
    const float* gw    = (const float*)d_in[1];  // [8,768]
    const float* bias  = (const float*)d_in[2];  // [8]
    const float* wgate = (const float*)d_in[3];  // [8,768,2688]
    const float* wup   = (const float*)d_in[4];  // [8,768,2688]
    const float* wdown = (const float*)d_in[5];  // [8,2688,768]
    float* out = (float*)d_out;

    k_init<<<1, 32>>>();
    k_cvt<<<1024, 256>>>(x, wgate, wup, wdown);
    k_router<<<T_TOK / 8, 256>>>(x, gw, bias);

    dim3 g1(T_TOK / 64, H_DIM / 64, E_NUM);    // 64 x 42 x 8 (M fastest -> weight-slab L2 reuse)
    k_gemm1<<<g1, 128>>>();

    dim3 g2(D_DIM / 128, T_TOK / 64, E_NUM);   // 6 x 64 x 8 (N fastest -> A-slab L2 reuse)
    k_gemm2<<<g2, 128>>>();

    k_combine<<<T_TOK, 192>>>(out);
    k_final<<<1, 1>>>(out, out_size);
}

// round 11
// speedup vs baseline: 6.9126x; 3.5389x over previous
#include <cuda_runtime.h>
#include <cuda_fp16.h>
#include <mma.h>
#include <cstdint>

using namespace nvcuda;

#define T_TOK 4096
#define D_DIM 768
#define H_DIM 2688
#define E_NUM 8
#define BK 32

// ---------------- scratch (static device globals; no allocations) ----------------
__device__ float g_z_acc;
__device__ int   g_cnt[E_NUM];
__device__ int   g_tok[E_NUM * T_TOK];
__device__ int   g_slot[2 * T_TOK];   // per token: two (expert*T_TOK + pos) slots
__device__ float g_wt [2 * T_TOK];    // per token: two softmax weights
// fp16 copies (RN)
__device__ __half g_xh [(size_t)T_TOK * D_DIM];
__device__ __half g_wgh[(size_t)E_NUM * D_DIM * H_DIM];
__device__ __half g_wuh[(size_t)E_NUM * D_DIM * H_DIM];
__device__ __half g_wdh[(size_t)E_NUM * H_DIM * D_DIM];
// act scratch: [E*T, H] fp16
__device__ __half g_acth[(size_t)E_NUM * T_TOK * H_DIM];
// per-slot down-proj result: [E*T, D] fp32
__device__ float g_y[(size_t)E_NUM * T_TOK * D_DIM];

__device__ __forceinline__ void cpa16(void* s, const void* g) {
    unsigned a = (unsigned)__cvta_generic_to_shared(s);
    asm volatile("cp.async.cg.shared.global [%0], [%1], 16;" :: "r"(a), "l"(g));
}
#define CP_COMMIT() asm volatile("cp.async.commit_group;" ::: "memory")
#define CP_WAIT1()  asm volatile("cp.async.wait_group 1;" ::: "memory")

// ---------------- kernel 0: init counters ----------------
__global__ void k_init() {
    if (threadIdx.x < E_NUM) g_cnt[threadIdx.x] = 0;
    if (threadIdx.x == 31)   g_z_acc = 0.0f;
}

// ---------------- kernel 0b: fp32 -> fp16 copies ----------------
__global__ void k_cvt(const float* __restrict__ x,
                      const float* __restrict__ wg,
                      const float* __restrict__ wu,
                      const float* __restrict__ wd) {
    const size_t i0 = (size_t)blockIdx.x * blockDim.x + threadIdx.x;
    const size_t st = (size_t)gridDim.x * blockDim.x;
    const size_t NX = (size_t)T_TOK * D_DIM / 4;
    const size_t NW = (size_t)E_NUM * D_DIM * H_DIM / 4;
    for (size_t i = i0; i < NX; i += st) {
        float4 v = ((const float4*)x)[i];
        ((__half2*)g_xh)[2 * i]     = __floats2half2_rn(v.x, v.y);
        ((__half2*)g_xh)[2 * i + 1] = __floats2half2_rn(v.z, v.w);
    }
    for (size_t i = i0; i < NW; i += st) {
        float4 v = ((const float4*)wg)[i];
        ((__half2*)g_wgh)[2 * i]     = __floats2half2_rn(v.x, v.y);
        ((__half2*)g_wgh)[2 * i + 1] = __floats2half2_rn(v.z, v.w);
    }
    for (size_t i = i0; i < NW; i += st) {
        float4 v = ((const float4*)wu)[i];
        ((__half2*)g_wuh)[2 * i]     = __floats2half2_rn(v.x, v.y);
        ((__half2*)g_wuh)[2 * i + 1] = __floats2half2_rn(v.z, v.w);
    }
    for (size_t i = i0; i < NW; i += st) {
        float4 v = ((const float4*)wd)[i];
        ((__half2*)g_wdh)[2 * i]     = __floats2half2_rn(v.x, v.y);
        ((__half2*)g_wdh)[2 * i + 1] = __floats2half2_rn(v.z, v.w);
    }
}

// ---------------- kernel 1: router ----------------
__global__ void k_router(const float* __restrict__ x,
                         const float* __restrict__ gw,
                         const float* __restrict__ bias) {
    int gwarp = (blockIdx.x * blockDim.x + threadIdx.x) >> 5;
    int lane  = threadIdx.x & 31;
    if (gwarp >= T_TOK) return;
    const float* xr = x + (size_t)gwarp * D_DIM;

    float xv[24];
#pragma unroll
    for (int i = 0; i < 24; i++) xv[i] = xr[i * 32 + lane];

    float lg[8];
#pragma unroll
    for (int e = 0; e < 8; e++) {
        const float* w = gw + e * D_DIM;
        float s = 0.0f;
#pragma unroll
        for (int i = 0; i < 24; i++) s += xv[i] * w[i * 32 + lane];
#pragma unroll
        for (int o = 16; o > 0; o >>= 1) s += __shfl_xor_sync(0xffffffffu, s, o);
        lg[e] = s;
    }

    if (lane == 0) {
        float b1 = -1e30f, b2 = -1e30f; int i1 = 0, i2 = 0;
#pragma unroll
        for (int e = 0; e < 8; e++) {
            float b = lg[e] + bias[e];
            if (b > b1)      { b2 = b1; i2 = i1; b1 = b; i1 = e; }
            else if (b > b2) { b2 = b;  i2 = e; }
        }
        float l1 = lg[i1], l2 = lg[i2];
        float m = fmaxf(l1, l2);
        float e1 = expf(l1 - m), e2 = expf(l2 - m);
        float inv = 1.0f / (e1 + e2);
        float w1 = e1 * inv, w2 = e2 * inv;

        float mm = lg[0];
#pragma unroll
        for (int e = 1; e < 8; e++) mm = fmaxf(mm, lg[e]);
        float s = 0.0f;
#pragma unroll
        for (int e = 0; e < 8; e++) s += expf(lg[e] - mm);
        float lse = mm + logf(s);
        atomicAdd(&g_z_acc, lse * lse);

        int p1 = atomicAdd(&g_cnt[i1], 1);
        g_tok[i1 * T_TOK + p1] = gwarp;
        g_slot[2 * gwarp + 0] = i1 * T_TOK + p1;
        g_wt  [2 * gwarp + 0] = w1;
        int p2 = atomicAdd(&g_cnt[i2], 1);
        g_tok[i2 * T_TOK + p2] = gwarp;
        g_slot[2 * gwarp + 1] = i2 * T_TOK + p2;
        g_wt  [2 * gwarp + 1] = w2;
    }
}

// ---------------- kernel 2: fp16 GEMM1, 64x64 tile, BK=32, cp.async 3-stage ----------------
// g = X*Wg, u = X*Wu (shared A), act = silu(g)*u -> g_acth (fp16)
__global__ void __launch_bounds__(128) k_gemm1() {
    const int e   = blockIdx.z;
    const int cnt = g_cnt[e];
    const int m0  = blockIdx.x * 64;
    if (m0 >= cnt) return;
    const int n0  = blockIdx.y * 64;

    __shared__ union {
        struct {
            __half A [3][64][40];   // 64 x 32 (+8 pad)
            __half Bg[3][32][72];   // 32 x 64 (+8 pad)
            __half Bu[3][32][72];
        } p;
        float C[64][68];            // fp32 epilogue staging
    } sm;

    const int tid  = threadIdx.x;
    const int warp = tid >> 5;
    const int wm   = warp >> 1;   // 0..1 -> 32-row slab
    const int wn   = warp & 1;    // 0..1 -> 32-col slab

    // A staging: 64 rows x 32 halves = 64B/row = 4 chunks/row -> 256 chunks, 2/thread
    int a_r[2], a_c[2];           // c in halves
    const __half* a_src[2];
#pragma unroll
    for (int q = 0; q < 2; q++) {
        int ch = q * 128 + tid;
        a_r[q] = ch >> 2; a_c[q] = (ch & 3) * 8;
        int row = m0 + a_r[q];
        int tok = g_tok[e * T_TOK + (row < cnt ? row : cnt - 1)];
        a_src[q] = g_xh + (size_t)tok * D_DIM + a_c[q];
    }
    // B staging: 32 rows x 64 halves = 128B/row = 8 chunks/row -> 256 chunks, 2/thread (each matrix)
    int b_r[2], b_c[2];
    const __half* bg_src[2]; const __half* bu_src[2];
    const size_t wb = (size_t)e * D_DIM * H_DIM;
#pragma unroll
    for (int q = 0; q < 2; q++) {
        int ch = q * 128 + tid;
        b_r[q] = ch >> 3; b_c[q] = (ch & 7) * 8;
        size_t o = wb + (size_t)b_r[q] * H_DIM + n0 + b_c[q];
        bg_src[q] = g_wgh + o;
        bu_src[q] = g_wuh + o;
    }

    wmma::fragment<wmma::accumulator, 16, 16, 16, float> accg[2][2], accu[2][2];
#pragma unroll
    for (int i = 0; i < 2; i++)
#pragma unroll
        for (int j = 0; j < 2; j++) {
            wmma::fill_fragment(accg[i][j], 0.0f);
            wmma::fill_fragment(accu[i][j], 0.0f);
        }

    auto issue = [&](int s, int kt) {
        const int k0 = kt * BK;
#pragma unroll
        for (int q = 0; q < 2; q++)
            cpa16(&sm.p.A[s][a_r[q]][a_c[q]], a_src[q] + k0);
#pragma unroll
        for (int q = 0; q < 2; q++) {
            const size_t o = (size_t)k0 * H_DIM;
            cpa16(&sm.p.Bg[s][b_r[q]][b_c[q]], bg_src[q] + o);
            cpa16(&sm.p.Bu[s][b_r[q]][b_c[q]], bu_src[q] + o);
        }
    };

    const int NK = D_DIM / BK;   // 24
    issue(0, 0); CP_COMMIT();
    issue(1, 1); CP_COMMIT();

    for (int kt = 0; kt < NK; kt++) {
        const int cur = kt % 3;
        CP_WAIT1();
        __syncthreads();
        if (kt + 2 < NK) issue((kt + 2) % 3, kt + 2);
        CP_COMMIT();
#pragma unroll
        for (int kk = 0; kk < 2; kk++) {
            wmma::fragment<wmma::matrix_a, 16, 16, 16, __half, wmma::row_major> af[2];
            wmma::fragment<wmma::matrix_b, 16, 16, 16, __half, wmma::row_major> bgf[2], buf2[2];
#pragma unroll
            for (int i = 0; i < 2; i++)
                wmma::load_matrix_sync(af[i], &sm.p.A[cur][wm * 32 + i * 16][kk * 16], 40);
#pragma unroll
            for (int j = 0; j < 2; j++) {
                wmma::load_matrix_sync(bgf[j],  &sm.p.Bg[cur][kk * 16][wn * 32 + j * 16], 72);
                wmma::load_matrix_sync(buf2[j], &sm.p.Bu[cur][kk * 16][wn * 32 + j * 16], 72);
            }
#pragma unroll
            for (int i = 0; i < 2; i++)
#pragma unroll
                for (int j = 0; j < 2; j++) {
                    wmma::mma_sync(accg[i][j], af[i], bgf[j],  accg[i][j]);
                    wmma::mma_sync(accu[i][j], af[i], buf2[j], accu[i][j]);
                }
        }
    }

    // epilogue: act = silu(g)*u (fp32 math), -> fp16 g_acth
    __syncthreads();
#pragma unroll
    for (int i = 0; i < 2; i++)
#pragma unroll
        for (int j = 0; j < 2; j++) {
#pragma unroll
            for (int t = 0; t < accg[i][j].num_elements; t++) {
                float g = accg[i][j].x[t];
                float u = accu[i][j].x[t];
                float sg = 1.0f / (1.0f + expf(-g));
                accg[i][j].x[t] = g * sg * u;
            }
            wmma::store_matrix_sync(&sm.C[wm * 32 + i * 16][wn * 32 + j * 16],
                                    accg[i][j], 68, wmma::mem_row_major);
        }
    __syncthreads();
    // 64x64 elems, half2 stores: 2048 pairs, 16/thread (junk rows in-bounds, never read)
    for (int idx = tid; idx < 64 * 32; idx += 128) {
        int r = idx >> 5, c2 = (idx & 31) * 2;
        __half2 h = __floats2half2_rn(sm.C[r][c2], sm.C[r][c2 + 1]);
        *(__half2*)(g_acth + ((size_t)e * T_TOK + m0 + r) * H_DIM + n0 + c2) = h;
    }
}

// ---------------- kernel 3: fp16 GEMM2, 64x128 tile, BK=32, cp.async 3-stage ----------------
__global__ void __launch_bounds__(128) k_gemm2() {
    const int e   = blockIdx.z;
    const int cnt = g_cnt[e];
    const int m0  = blockIdx.y * 64;
    if (m0 >= cnt) return;
    const int n0  = blockIdx.x * 128;

    __shared__ __half sA[3][64][40];     // 64 x 32 (+8)
    __shared__ __half sB[3][32][136];    // 32 x 128 (+8)

    const int tid  = threadIdx.x;
    const int warp = tid >> 5;
    const int wm   = warp >> 1;   // 0..1 -> 32-row slab
    const int wn   = warp & 1;    // 0..1 -> 64-col slab

    // A: 256 chunks, 2/thread (from fp16 act, dense slot rows)
    int a_r[2], a_c[2];
    const __half* a_src[2];
#pragma unroll
    for (int q = 0; q < 2; q++) {
        int ch = q * 128 + tid;
        a_r[q] = ch >> 2; a_c[q] = (ch & 3) * 8;
        a_src[q] = g_acth + ((size_t)e * T_TOK + m0 + a_r[q]) * H_DIM + a_c[q];
    }
    // B: 32 rows x 128 halves = 16 chunks/row -> 512 chunks, 4/thread
    int b_r[4], b_c[4];
    const __half* b_src[4];
    const size_t wb = (size_t)e * H_DIM * D_DIM;
#pragma unroll
    for (int q = 0; q < 4; q++) {
        int ch = q * 128 + tid;
        b_r[q] = ch >> 4; b_c[q] = (ch & 15) * 8;
        b_src[q] = g_wdh + wb + (size_t)b_r[q] * D_DIM + n0 + b_c[q];
    }

    wmma::fragment<wmma::accumulator, 16, 16, 16, float> acc[2][4];
#pragma unroll
    for (int i = 0; i < 2; i++)
#pragma unroll
        for (int j = 0; j < 4; j++) wmma::fill_fragment(acc[i][j], 0.0f);

    auto issue = [&](int s, int kt) {
        const int k0 = kt * BK;
#pragma unroll
        for (int q = 0; q < 2; q++)
            cpa16(&sA[s][a_r[q]][a_c[q]], a_src[q] + k0);
#pragma unroll
        for (int q = 0; q < 4; q++)
            cpa16(&sB[s][b_r[q]][b_c[q]], b_src[q] + (size_t)k0 * D_DIM);
    };

    const int NK = H_DIM / BK;   // 84
    issue(0, 0); CP_COMMIT();
    issue(1, 1); CP_COMMIT();

    for (int kt = 0; kt < NK; kt++) {
        const int cur = kt % 3;
        CP_WAIT1();
        __syncthreads();
        if (kt + 2 < NK) issue((kt + 2) % 3, kt + 2);
        CP_COMMIT();
#pragma unroll
        for (int kk = 0; kk < 2; kk++) {
            wmma::fragment<wmma::matrix_a, 16, 16, 16, __half, wmma::row_major> af[2];
            wmma::fragment<wmma::matrix_b, 16, 16, 16, __half, wmma::row_major> bf[4];
#pragma unroll
            for (int i = 0; i < 2; i++)
                wmma::load_matrix_sync(af[i], &sA[cur][wm * 32 + i * 16][kk * 16], 40);
#pragma unroll
            for (int j = 0; j < 4; j++)
                wmma::load_matrix_sync(bf[j], &sB[cur][kk * 16][wn * 64 + j * 16], 136);
#pragma unroll
            for (int i = 0; i < 2; i++)
#pragma unroll
                for (int j = 0; j < 4; j++)
                    wmma::mma_sync(acc[i][j], af[i], bf[j], acc[i][j]);
        }
    }

    // epilogue: per-slot fp32 result direct to g_y (no atomics; junk rows never combined)
    float* ybase = g_y + ((size_t)e * T_TOK + m0) * D_DIM + n0;
#pragma unroll
    for (int i = 0; i < 2; i++)
#pragma unroll
        for (int j = 0; j < 4; j++)
            wmma::store_matrix_sync(ybase + (size_t)(wm * 32 + i * 16) * D_DIM + wn * 64 + j * 16,
                                    acc[i][j], D_DIM, wmma::mem_row_major);
}

// ---------------- kernel 4: combine two expert slots per token ----------------
__global__ void k_combine(float* __restrict__ out) {
    const int t = blockIdx.x;
    const int s0 = g_slot[2 * t], s1 = g_slot[2 * t + 1];
    const float w0 = g_wt[2 * t], w1 = g_wt[2 * t + 1];
    const float4* y0 = (const float4*)(g_y + (size_t)s0 * D_DIM);
    const float4* y1 = (const float4*)(g_y + (size_t)s1 * D_DIM);
    float4 a = y0[threadIdx.x];
    float4 b = y1[threadIdx.x];
    float4 r;
    r.x = w0 * a.x + w1 * b.x;
    r.y = w0 * a.y + w1 * b.y;
    r.z = w0 * a.z + w1 * b.z;
    r.w = w0 * a.w + w1 * b.w;
    ((float4*)(out + (size_t)t * D_DIM))[threadIdx.x] = r;
}

// ---------------- kernel 5: finalize z-loss ----------------
__global__ void k_final(float* __restrict__ out, int out_size) {
    if (out_size > T_TOK * D_DIM)
        out[T_TOK * D_DIM] = 1e-5f * g_z_acc / (float)T_TOK;
}

// ---------------- launcher ----------------
extern "C" void kernel_launch(void* const* d_in, const int* in_sizes, int n_in,
                              void* d_out, int out_size) {
    const float* x     = (const float*)d_in[0];  // [2,2048,768]
    const float* gw    = (const float*)d_in[1];  // [8,768]
    const float* bias  = (const float*)d_in[2];  // [8]
    const float* wgate = (const float*)d_in[3];  // [8,768,2688]
    const float* wup   = (const float*)d_in[4];  // [8,768,2688]
    const float* wdown = (const float*)d_in[5];  // [8,2688,768]
    float* out = (float*)d_out;

    k_init<<<1, 32>>>();
    k_cvt<<<1024, 256>>>(x, wgate, wup, wdown);
    k_router<<<T_TOK / 8, 256>>>(x, gw, bias);

    dim3 g1(T_TOK / 64, H_DIM / 64, E_NUM);    // 64 x 42 x 8 (M fastest -> weight-slab L2 reuse)
    k_gemm1<<<g1, 128>>>();

    dim3 g2(D_DIM / 128, T_TOK / 64, E_NUM);   // 6 x 64 x 8 (N fastest -> A-slab L2 reuse)
    k_gemm2<<<g2, 128>>>();

    k_combine<<<T_TOK, 192>>>(out);
    k_final<<<1, 1>>>(out, out_size);
}